// round 15
// baseline (speedup 1.0000x reference)
#include <cuda_runtime.h>
#include <math.h>

#define HD 256
#define AD 64
#define VOCAB 32000
#define TS 64
#define BB 32
#define SQ 1024
#define H2 512
#define ROWS_TOT (TS*BB)
#define NB 64
#define NTILE 250

__device__ float g_embT[TS*HD*BB];             // [t][i][b]
__device__ float g_hT[2*HD*BB];                // ping-pong [p][k][b]
__device__ float g_ctxT[2*HD*BB];              // ping-pong [p][h][b]
__device__ float g_hid[HD*BB];                 // [j][b]
__device__ float g_c2[(size_t)BB*AD*SQ];       // [b][a][s]
__device__ float g_obuf[(size_t)ROWS_TOT*H2];
__device__ float g_qT[(size_t)HD*ROWS_TOT];    // fc1 out, k-major [k][r]
__device__ float g_f1w2T[HD*AD];
__device__ float g_f2w1T[HD*HD];
__device__ float g_f2w2T[HD*AD];
__device__ float g_fc1wT[H2*HD];
__device__ float g_fc2wT[(size_t)HD*VOCAB];
__device__ float g_pm[(size_t)ROWS_TOT*NTILE]; // per-(row,tile) max
__device__ float g_ps[(size_t)ROWS_TOT*NTILE]; // per-(row,tile) sumexp
__device__ float g_nll[ROWS_TOT];
__device__ float g_msk[ROWS_TOT];
__device__ unsigned g_bar;

__device__ __forceinline__ float2 ffma2(float2 a, float2 b, float2 c) {
    union U { float2 f; unsigned long long u; };
    U ua, ub, uc, ud; ua.f = a; ub.f = b; uc.f = c;
    asm("fma.rn.f32x2 %0, %1, %2, %3;" : "=l"(ud.u) : "l"(ua.u), "l"(ub.u), "l"(uc.u));
    return ud.f;
}
__device__ __forceinline__ float2 b2f(float w) { return make_float2(w, w); }
__device__ __forceinline__ float2 add2(float2 a, float2 b) { return make_float2(a.x+b.x, a.y+b.y); }

// ---- launch 1: fused prep: zero + small transposes + embT + fc2 transpose ----
__global__ void k_prep(const float* __restrict__ f2w1, const float* __restrict__ f2w2,
                       const float* __restrict__ f1w2, const float* __restrict__ fc1w,
                       const float* __restrict__ fc2w,
                       const int* __restrict__ yin, const float* __restrict__ emb) {
    __shared__ float tile[32][33];
    int bid = blockIdx.x, tid = threadIdx.x;
    if (bid == 0) {
        for (int i = tid; i < 2*HD*BB; i += 256) { g_hT[i] = 0.f; g_ctxT[i] = 0.f; }
        if (tid == 0) g_bar = 0u;
        return;
    }
    if (bid >= 289) {   // fc2 weight transpose: 8000 blocks
        int r2 = bid - 289;
        int bx = r2 & 7, by = r2 >> 3;
        int tx = tid & 31, ty = tid >> 5;
        int c0 = bx*32, r0 = by*32;
        for (int j = ty; j < 32; j += 8)
            tile[j][tx] = fc2w[(size_t)(r0 + j)*HD + c0 + tx];
        __syncthreads();
        for (int j = ty; j < 32; j += 8)
            g_fc2wT[(size_t)(c0 + j)*VOCAB + r0 + tx] = tile[tx][j];
        return;
    }
    if (bid >= 225) {   // embT: 64 blocks
        int t = bid - 225, i = tid;
        for (int b = 0; b < BB; b++)
            g_embT[((size_t)t*HD + i)*BB + b] = emb[(size_t)yin[t*BB + b]*HD + i];
        return;
    }
    const float* src; float* dst; int rows, cols, nbx;
    int r = bid - 1;
    if (r < 64)       { src = f2w1; dst = g_f2w1T; rows = HD; cols = HD; nbx = 8; }
    else if (r < 80)  { r -= 64; src = f2w2; dst = g_f2w2T; rows = AD; cols = HD; nbx = 8; }
    else if (r < 96)  { r -= 80; src = f1w2; dst = g_f1w2T; rows = AD; cols = HD; nbx = 8; }
    else              { r -= 96; src = fc1w; dst = g_fc1wT; rows = HD; cols = H2; nbx = 16; }
    int bx = r % nbx, by = r / nbx;
    int tx = tid & 31, ty = tid >> 5;
    int c0 = bx*32, r0 = by*32;
    for (int j = ty; j < 32; j += 8) {
        int rr = r0 + j, c = c0 + tx;
        if (rr < rows && c < cols) tile[j][tx] = src[(size_t)rr*cols + c];
    }
    __syncthreads();
    for (int j = ty; j < 32; j += 8) {
        int rr = r0 + tx, c = c0 + j;
        if (rr < rows && c < cols) dst[(size_t)c*rows + rr] = tile[tx][j];
    }
}

// ---- launch 2: c2, stored [b][a][s] ----
__global__ void k_c2(const float* __restrict__ yenc,
                     const float* __restrict__ b1, const float* __restrict__ b2) {
    __shared__ float2 ysp[HD][8];
    __shared__ float  hid[16][HD];
    int r0 = blockIdx.x*16, tid = threadIdx.x;
    float* ysf = (float*)ysp;
    for (int idx = tid; idx < 16*HD; idx += 256) {
        int r = idx >> 8, i = idx & 255;
        ysf[i*16 + r] = yenc[(size_t)(r0+r)*HD + i];
    }
    __syncthreads();
    {
        int j = tid; float bj = b1[j];
        float2 acc[8];
        #pragma unroll
        for (int p = 0; p < 8; p++) acc[p] = make_float2(bj, bj);
        for (int i = 0; i < HD; i++) {
            float2 wp = b2f(g_f2w1T[i*HD + j]);
            #pragma unroll
            for (int p = 0; p < 8; p++) acc[p] = ffma2(wp, ysp[i][p], acc[p]);
        }
        #pragma unroll
        for (int p = 0; p < 8; p++) {
            hid[2*p][j]   = fmaxf(acc[p].x, 0.f);
            hid[2*p+1][j] = fmaxf(acc[p].y, 0.f);
        }
    }
    __syncthreads();
    #pragma unroll
    for (int q = 0; q < 4; q++) {
        int o = tid + q*256, rr = o >> 6, a = o & 63;
        float acc = b2[a];
        for (int i = 0; i < HD; i++) acc = fmaf(hid[rr][i], g_f2w2T[i*AD + a], acc);
        int gr = r0 + rr, s = gr >> 5, b = gr & 31;
        g_c2[((size_t)b*AD + a)*SQ + s] = tanhf(acc);
    }
}

// ---- launch 3: persistent decode loop, 64 blocks x 256 threads (2982us exact) ----
__global__ void __launch_bounds__(256, 1)
k_loop(const float* __restrict__ yenc,
       const float* __restrict__ wih, const float* __restrict__ bih,
       const float* __restrict__ whh, const float* __restrict__ bhh,
       const float* __restrict__ f1w1, const float* __restrict__ f1b1,
       const float* __restrict__ f1b2) {
    extern __shared__ float sdyn[];
    float2* sm2 = (float2*)sdyn;
    __shared__ float2 red[4][4][16][4];
    __shared__ float hred[256];
    __shared__ float s_hid[HD];
    __shared__ float c1s[AD];
    __shared__ float attw[SQ];
    __shared__ float2 cred[8][32][2];
    __shared__ float rsh[8];
    __shared__ float sh_mx, sh_sum;

    int g = blockIdx.x, tid = threadIdx.x;
    int kl = tid >> 6, ph = (tid >> 4) & 3, bp = tid & 15;
    int k = g*4 + kl;
    int ab = g >> 1, half = g & 1;
    unsigned bar = 0;
    const float* wihR = wih + (size_t)k*H2;
    const float* wihZ = wih + (size_t)(HD + k)*H2;
    const float* wihN = wih + (size_t)(2*HD + k)*H2;
    const float* whhR = whh + (size_t)k*HD;
    const float* whhZ = whh + (size_t)(HD + k)*HD;
    const float* whhN = whh + (size_t)(2*HD + k)*HD;
    const float2 z2 = make_float2(0.f, 0.f);

    for (int t = 0; t < TS; t++) {
        int cur = t & 1, nxt = cur ^ 1;
        {
            float4* d = (float4*)sdyn;
            const float4* se = (const float4*)(g_embT) + (size_t)t*2048;
            const float4* sc = (const float4*)(g_ctxT + (size_t)cur*HD*BB);
            const float4* sh = (const float4*)(g_hT   + (size_t)cur*HD*BB);
            for (int i = tid; i < 2048; i += 256) {
                d[i]        = se[i];
                d[2048 + i] = __ldcg(sc + i);
                d[4096 + i] = __ldcg(sh + i);
            }
        }
        __syncthreads();
        // ---- phase G: GRU ----
        {
            float2 ar = z2, az = z2, ani = z2, anh = z2;
            int pst = ph*192, pen = pst + 192;
            int mid = pen < 512 ? pen : (pst > 512 ? pst : 512);
            for (int p0 = pst; p0 < mid; p0 += 4) {
                float2 x0 = sm2[(p0+0)*16+bp], x1 = sm2[(p0+1)*16+bp];
                float2 x2 = sm2[(p0+2)*16+bp], x3 = sm2[(p0+3)*16+bp];
                float4 fr = *(const float4*)(wihR + p0);
                float4 fz = *(const float4*)(wihZ + p0);
                float4 fn = *(const float4*)(wihN + p0);
                ar = ffma2(b2f(fr.x),x0,ar); ar = ffma2(b2f(fr.y),x1,ar); ar = ffma2(b2f(fr.z),x2,ar); ar = ffma2(b2f(fr.w),x3,ar);
                az = ffma2(b2f(fz.x),x0,az); az = ffma2(b2f(fz.y),x1,az); az = ffma2(b2f(fz.z),x2,az); az = ffma2(b2f(fz.w),x3,az);
                ani= ffma2(b2f(fn.x),x0,ani);ani= ffma2(b2f(fn.y),x1,ani);ani= ffma2(b2f(fn.z),x2,ani);ani= ffma2(b2f(fn.w),x3,ani);
            }
            for (int p0 = mid; p0 < pen; p0 += 4) {
                float2 x0 = sm2[(p0+0)*16+bp], x1 = sm2[(p0+1)*16+bp];
                float2 x2 = sm2[(p0+2)*16+bp], x3 = sm2[(p0+3)*16+bp];
                int q = p0 - 512;
                float4 fr = *(const float4*)(whhR + q);
                float4 fz = *(const float4*)(whhZ + q);
                float4 fn = *(const float4*)(whhN + q);
                ar = ffma2(b2f(fr.x),x0,ar); ar = ffma2(b2f(fr.y),x1,ar); ar = ffma2(b2f(fr.z),x2,ar); ar = ffma2(b2f(fr.w),x3,ar);
                az = ffma2(b2f(fz.x),x0,az); az = ffma2(b2f(fz.y),x1,az); az = ffma2(b2f(fz.z),x2,az); az = ffma2(b2f(fz.w),x3,az);
                anh= ffma2(b2f(fn.x),x0,anh);anh= ffma2(b2f(fn.y),x1,anh);anh= ffma2(b2f(fn.z),x2,anh);anh= ffma2(b2f(fn.w),x3,anh);
            }
            red[ph][kl][bp][0] = ar; red[ph][kl][bp][1] = az;
            red[ph][kl][bp][2] = ani; red[ph][kl][bp][3] = anh;
        }
        __syncthreads();
        if (tid < 64) {
            int kk = tid >> 4, bq = tid & 15;
            int kg = g*4 + kk;
            float2 ar = z2, az = z2, ani = z2, anh = z2;
            #pragma unroll
            for (int q = 0; q < 4; q++) {
                ar  = add2(ar,  red[q][kk][bq][0]);
                az  = add2(az,  red[q][kk][bq][1]);
                ani = add2(ani, red[q][kk][bq][2]);
                anh = add2(anh, red[q][kk][bq][3]);
            }
            float br = bih[kg] + bhh[kg], bz = bih[HD+kg] + bhh[HD+kg];
            float bin = bih[2*HD+kg], bhn = bhh[2*HD+kg];
            float2 hprev = sm2[(512 + kg)*16 + bq];
            float rx = 1.f/(1.f + expf(-(ar.x + br)));
            float ry = 1.f/(1.f + expf(-(ar.y + br)));
            float zx = 1.f/(1.f + expf(-(az.x + bz)));
            float zy = 1.f/(1.f + expf(-(az.y + bz)));
            float nx = tanhf(ani.x + bin + rx*(anh.x + bhn));
            float ny = tanhf(ani.y + bin + ry*(anh.y + bhn));
            float2 hn = make_float2((1.f-zx)*nx + zx*hprev.x, (1.f-zy)*ny + zy*hprev.y);
            __stcg((float2*)(g_hT + (size_t)nxt*HD*BB) + (kg*16 + bq), hn);
            g_obuf[((size_t)t*BB + 2*bq)*H2 + kg]   = hn.x;
            g_obuf[((size_t)t*BB + 2*bq+1)*H2 + kg] = hn.y;
        }
        __syncthreads();
        if (tid == 0) { __threadfence(); atomicAdd(&g_bar, 1u);
            unsigned v; bar += NB;
            do { asm volatile("ld.acquire.gpu.b32 %0,[%1];":"=r"(v):"l"(&g_bar):"memory"); } while (v < bar);
        } else bar += NB;
        __syncthreads();

        // ---- phase H ----
        {
            float4* d = (float4*)sdyn;
            const float4* hn = (const float4*)(g_hT + (size_t)nxt*HD*BB);
            for (int i = tid; i < 2048; i += 256) d[i] = __ldcg(hn + i);
            __syncthreads();
            int hf = tid >> 7, jj = (tid >> 5) & 3, b = tid & 31;
            int j = g*4 + jj;
            const float* w = f1w1 + (size_t)j*HD + hf*128;
            float acc = 0.f;
            #pragma unroll 8
            for (int i4 = 0; i4 < 32; i4++) {
                float4 w4 = *(const float4*)(w + 4*i4);
                int ib = (hf*128 + 4*i4)*32 + b;
                acc = fmaf(w4.x, sdyn[ib],      acc);
                acc = fmaf(w4.y, sdyn[ib+32],   acc);
                acc = fmaf(w4.z, sdyn[ib+64],   acc);
                acc = fmaf(w4.w, sdyn[ib+96],   acc);
            }
            hred[tid] = acc;
        }
        __syncthreads();
        if (tid < 128) {
            int j = g*4 + (tid >> 5), b = tid & 31;
            float v = hred[tid] + hred[tid + 128] + f1b1[j];
            __stcg(&g_hid[j*32 + b], fmaxf(v, 0.f));
        }
        __syncthreads();
        if (tid == 0) { __threadfence(); atomicAdd(&g_bar, 1u);
            unsigned v; bar += NB;
            do { asm volatile("ld.acquire.gpu.b32 %0,[%1];":"=r"(v):"l"(&g_bar):"memory"); } while (v < bar);
        } else bar += NB;
        __syncthreads();

        // ---- phase A ----
        s_hid[tid] = __ldcg(&g_hid[tid*32 + ab]);
        __syncthreads();
        if (tid < AD) {
            float acc = 0.f;
            #pragma unroll 8
            for (int i = 0; i < HD; i++) acc = fmaf(g_f1w2T[i*AD + tid], s_hid[i], acc);
            c1s[tid] = tanhf(acc + f1b2[tid]);
        }
        __syncthreads();
        {
            int s0 = 4*tid;
            const float* c2b = g_c2 + (size_t)ab*AD*SQ;
            float4 sc = make_float4(0.f, 0.f, 0.f, 0.f);
            for (int a0 = 0; a0 < AD; a0 += 8) {
                float4 v[8];
                #pragma unroll
                for (int u = 0; u < 8; u++) v[u] = *(const float4*)(c2b + (size_t)(a0+u)*SQ + s0);
                #pragma unroll
                for (int u = 0; u < 8; u++) {
                    float ca = c1s[a0+u];
                    sc.x = fmaf(ca, v[u].x, sc.x); sc.y = fmaf(ca, v[u].y, sc.y);
                    sc.z = fmaf(ca, v[u].z, sc.z); sc.w = fmaf(ca, v[u].w, sc.w);
                }
            }
            float mloc = fmaxf(fmaxf(sc.x, sc.y), fmaxf(sc.z, sc.w));
            #pragma unroll
            for (int o = 16; o; o >>= 1) mloc = fmaxf(mloc, __shfl_xor_sync(~0u, mloc, o));
            if ((tid & 31) == 0) rsh[tid >> 5] = mloc;
            __syncthreads();
            if (tid == 0) { float v = rsh[0]; for (int w = 1; w < 8; w++) v = fmaxf(v, rsh[w]); sh_mx = v; }
            __syncthreads();
            float mx = sh_mx;
            sc.x = __expf(sc.x - mx); sc.y = __expf(sc.y - mx);
            sc.z = __expf(sc.z - mx); sc.w = __expf(sc.w - mx);
            float sl = sc.x + sc.y + sc.z + sc.w;
            #pragma unroll
            for (int o = 16; o; o >>= 1) sl += __shfl_xor_sync(~0u, sl, o);
            if ((tid & 31) == 0) rsh[tid >> 5] = sl;
            __syncthreads();
            if (tid == 0) { float v = 0.f; for (int w = 0; w < 8; w++) v += rsh[w]; sh_sum = v; }
            __syncthreads();
            float inv = 1.f / sh_sum;
            *(float4*)&attw[s0] = make_float4(sc.x*inv, sc.y*inv, sc.z*inv, sc.w*inv);
        }
        __syncthreads();
        {
            int v = tid & 31, strip = tid >> 5;
            int h0 = half*128;
            float2 a0 = z2, a1 = z2;
            for (int o8 = 0; o8 < 128; o8 += 8) {
                float4 y[8]; float aw[8];
                #pragma unroll
                for (int u = 0; u < 8; u++) {
                    int s = strip*128 + o8 + u;
                    y[u] = *(const float4*)(yenc + ((size_t)s*BB + ab)*HD + h0 + 4*v);
                    aw[u] = attw[s];
                }
                #pragma unroll
                for (int u = 0; u < 8; u++) {
                    a0 = ffma2(b2f(aw[u]), make_float2(y[u].x, y[u].y), a0);
                    a1 = ffma2(b2f(aw[u]), make_float2(y[u].z, y[u].w), a1);
                }
            }
            cred[strip][v][0] = a0; cred[strip][v][1] = a1;
            __syncthreads();
            if (tid < 32) {
                float2 s0 = z2, s1 = z2;
                #pragma unroll
                for (int w = 0; w < 8; w++) { s0 = add2(s0, cred[w][tid][0]); s1 = add2(s1, cred[w][tid][1]); }
                int hh = h0 + 4*tid;
                float* cb = g_ctxT + (size_t)nxt*HD*BB;
                __stcg(&cb[(hh+0)*32 + ab], s0.x);
                __stcg(&cb[(hh+1)*32 + ab], s0.y);
                __stcg(&cb[(hh+2)*32 + ab], s1.x);
                __stcg(&cb[(hh+3)*32 + ab], s1.y);
                *(float4*)&g_obuf[((size_t)t*BB + ab)*H2 + HD + hh] = make_float4(s0.x, s0.y, s1.x, s1.y);
            }
        }
        __syncthreads();
        if (tid == 0) { __threadfence(); atomicAdd(&g_bar, 1u);
            unsigned v; bar += NB;
            do { asm volatile("ld.acquire.gpu.b32 %0,[%1];":"=r"(v):"l"(&g_bar):"memory"); } while (v < bar);
        } else bar += NB;
        __syncthreads();
    }
}

// ---- launch 4: fc1 -> g_qT (k-major) ----
__global__ void k_fc1(const float* __restrict__ fc1b) {
    __shared__ float2 xsp[H2][8];
    int r0 = blockIdx.x*16, tid = threadIdx.x;
    float* xsf = (float*)xsp;
    for (int idx = tid; idx < 16*H2; idx += 256) {
        int r = idx >> 9, i = idx & 511;
        xsf[i*16 + r] = g_obuf[(size_t)(r0+r)*H2 + i];
    }
    __syncthreads();
    int j = tid; float bj = fc1b[j];
    float2 acc[8];
    #pragma unroll
    for (int p = 0; p < 8; p++) acc[p] = make_float2(bj, bj);
    for (int i = 0; i < H2; i++) {
        float2 wp = b2f(g_fc1wT[i*HD + j]);
        #pragma unroll
        for (int p = 0; p < 8; p++) acc[p] = ffma2(wp, xsp[i][p], acc[p]);
    }
    #pragma unroll
    for (int p = 0; p < 8; p++) {
        g_qT[(size_t)j*ROWS_TOT + r0 + 2*p]   = fmaxf(acc[p].x, 0.f);
        g_qT[(size_t)j*ROWS_TOT + r0 + 2*p+1] = fmaxf(acc[p].y, 0.f);
    }
}

// ---- launch 5: tiled fc2, 128x128 tile, 8x8 micro-tile + fused softmax partials ----
#define FBM 128
#define FBN 128
#define FKC 32
__global__ void __launch_bounds__(256) k_fc2(const float* __restrict__ fc2b, float* __restrict__ preds) {
    __shared__ float qs[FKC][FBM];
    __shared__ float ws[FKC][FBN];
    int tid = threadIdx.x;
    int tile = blockIdx.x;
    int nb = tile * FBN, rb = blockIdx.y * FBM;
    int tm = tid >> 4, tn = tid & 15;          // 16x16 thread grid
    float2 acc[8][4];
    #pragma unroll
    for (int i = 0; i < 8; i++)
        #pragma unroll
        for (int c = 0; c < 4; c++) acc[i][c] = make_float2(0.f, 0.f);
    for (int kc = 0; kc < HD; kc += FKC) {
        __syncthreads();
        #pragma unroll
        for (int u = 0; u < 4; u++) {
            int idx = tid + u*256;             // 1024 float4 each
            int kk = idx >> 5, rf = idx & 31;
            *(float4*)&qs[kk][rf*4] = *(const float4*)&g_qT[(size_t)(kc+kk)*ROWS_TOT + rb + rf*4];
            *(float4*)&ws[kk][rf*4] = *(const float4*)&g_fc2wT[(size_t)(kc+kk)*VOCAB + nb + rf*4];
        }
        __syncthreads();
        #pragma unroll 2
        for (int kk = 0; kk < FKC; kk++) {
            float4 a0 = *(const float4*)&qs[kk][tm*8];
            float4 a1 = *(const float4*)&qs[kk][tm*8 + 4];
            float4 w0 = *(const float4*)&ws[kk][tn*8];
            float4 w1 = *(const float4*)&ws[kk][tn*8 + 4];
            float2 b01 = make_float2(w0.x, w0.y), b23 = make_float2(w0.z, w0.w);
            float2 b45 = make_float2(w1.x, w1.y), b67 = make_float2(w1.z, w1.w);
            float av[8] = {a0.x, a0.y, a0.z, a0.w, a1.x, a1.y, a1.z, a1.w};
            #pragma unroll
            for (int i = 0; i < 8; i++) {
                float2 ap = b2f(av[i]);
                acc[i][0] = ffma2(ap, b01, acc[i][0]);
                acc[i][1] = ffma2(ap, b23, acc[i][1]);
                acc[i][2] = ffma2(ap, b45, acc[i][2]);
                acc[i][3] = ffma2(ap, b67, acc[i][3]);
            }
        }
    }
    int n0 = nb + tn*8;
    float4 bv0 = *(const float4*)&fc2b[n0];
    float4 bv1 = *(const float4*)&fc2b[n0 + 4];
    #pragma unroll
    for (int i = 0; i < 8; i++) {
        int row = rb + tm*8 + i;
        float4 lo = make_float4(acc[i][0].x + bv0.x, acc[i][0].y + bv0.y,
                                acc[i][1].x + bv0.z, acc[i][1].y + bv0.w);
        float4 hi = make_float4(acc[i][2].x + bv1.x, acc[i][2].y + bv1.y,
                                acc[i][3].x + bv1.z, acc[i][3].y + bv1.w);
        *(float4*)&preds[(size_t)row*VOCAB + n0]     = lo;
        *(float4*)&preds[(size_t)row*VOCAB + n0 + 4] = hi;
        // per-row partial softmax over this block's 128 cols: 16-lane group (tn)
        float lm = fmaxf(fmaxf(fmaxf(lo.x, lo.y), fmaxf(lo.z, lo.w)),
                         fmaxf(fmaxf(hi.x, hi.y), fmaxf(hi.z, hi.w)));
        #pragma unroll
        for (int of = 8; of; of >>= 1) lm = fmaxf(lm, __shfl_xor_sync(~0u, lm, of));
        float se = __expf(lo.x - lm) + __expf(lo.y - lm) + __expf(lo.z - lm) + __expf(lo.w - lm)
                 + __expf(hi.x - lm) + __expf(hi.y - lm) + __expf(hi.z - lm) + __expf(hi.w - lm);
        #pragma unroll
        for (int of = 8; of; of >>= 1) se += __shfl_xor_sync(~0u, se, of);
        if (tn == 0) {
            g_pm[(size_t)row*NTILE + tile] = lm;
            g_ps[(size_t)row*NTILE + tile] = se;
        }
    }
}

// ---- launch 6: combine per-tile partials -> nll ----
__global__ void k_loss_combine(const float* __restrict__ preds, const int* __restrict__ yout) {
    __shared__ float rm[8], rs[8];
    int row = blockIdx.x, tid = threadIdx.x;
    float m = -1e30f, s = 0.f;
    if (tid < NTILE) {
        m = g_pm[(size_t)row*NTILE + tid];
        s = g_ps[(size_t)row*NTILE + tid];
    }
    #pragma unroll
    for (int o = 16; o; o >>= 1) {
        float mo = __shfl_xor_sync(~0u, m, o);
        float so = __shfl_xor_sync(~0u, s, o);
        float nm = fmaxf(m, mo);
        s = s*__expf(m - nm) + so*__expf(mo - nm);
        m = nm;
    }
    if ((tid & 31) == 0) { rm[tid >> 5] = m; rs[tid >> 5] = s; }
    __syncthreads();
    if (tid == 0) {
        float M = rm[0], S = rs[0];
        for (int w = 1; w < 8; w++) {
            float nm = fmaxf(M, rm[w]);
            S = S*__expf(M - nm) + rs[w]*__expf(rm[w] - nm);
            M = nm;
        }
        int tgt = yout[row];
        float msk = (tgt != 0) ? 1.f : 0.f;
        g_nll[row] = (M + logf(S) - preds[(size_t)row*VOCAB + tgt]) * msk;
        g_msk[row] = msk;
    }
}

// ---- launch 7: final loss reduce ----
__global__ void k_loss_final(float* __restrict__ out, int oi) {
    __shared__ float ra[8], rb[8];
    int tid = threadIdx.x;
    float a = 0.f, b = 0.f;
    for (int r = tid; r < ROWS_TOT; r += 256) { a += g_nll[r]; b += g_msk[r]; }
    #pragma unroll
    for (int o = 16; o; o >>= 1) { a += __shfl_xor_sync(~0u, a, o); b += __shfl_xor_sync(~0u, b, o); }
    if ((tid & 31) == 0) { ra[tid >> 5] = a; rb[tid >> 5] = b; }
    __syncthreads();
    if (tid == 0) {
        float sa = 0.f, sb = 0.f;
        for (int w = 0; w < 8; w++) { sa += ra[w]; sb += rb[w]; }
        out[oi] = sa / fmaxf(sb, 1.f);
    }
}

extern "C" void kernel_launch(void* const* d_in, const int* in_sizes, int n_in,
                              void* d_out, int out_size) {
    const int*   y_in  = (const int*)  d_in[0];
    const int*   y_out = (const int*)  d_in[1];
    const float* y_enc = (const float*)d_in[2];
    const float* emb   = (const float*)d_in[4];
    const float* f1_w1 = (const float*)d_in[5];
    const float* f1_b1 = (const float*)d_in[6];
    const float* f1_w2 = (const float*)d_in[7];
    const float* f1_b2 = (const float*)d_in[8];
    const float* f2_w1 = (const float*)d_in[9];
    const float* f2_b1 = (const float*)d_in[10];
    const float* f2_w2 = (const float*)d_in[11];
    const float* f2_b2 = (const float*)d_in[12];
    const float* g_wih = (const float*)d_in[13];
    const float* g_bih = (const float*)d_in[14];
    const float* g_whh = (const float*)d_in[15];
    const float* g_bhh = (const float*)d_in[16];
    const float* fc1_w = (const float*)d_in[17];
    const float* fc1_b = (const float*)d_in[18];
    const float* fc2_w = (const float*)d_in[19];
    const float* fc2_b = (const float*)d_in[20];

    float* preds = (float*)d_out;
    const long long TBV = (long long)TS*BB*VOCAB;

    cudaFuncSetAttribute(k_loop, cudaFuncAttributeMaxDynamicSharedMemorySize, 98304);

    k_prep<<<289 + 8000, 256>>>(f2_w1, f2_w2, f1_w2, fc1_w, fc2_w, y_in, emb); // 1
    k_c2<<<(SQ*BB)/16, 256>>>(y_enc, f2_b1, f2_b2);                            // 2
    k_loop<<<NB, 256, 98304>>>(y_enc, g_wih, g_bih, g_whh, g_bhh,
                               f1_w1, f1_b1, f1_b2);                           // 3
    k_fc1<<<ROWS_TOT/16, 256>>>(fc1_b);                                        // 4
    k_fc2<<<dim3(NTILE, ROWS_TOT/FBM), 256>>>(fc2_b, preds);                   // 5
    if ((long long)out_size >= TBV + 1) {
        k_loss_combine<<<ROWS_TOT, 256>>>(preds, y_out);                       // 6
        k_loss_final<<<1, 256>>>(preds, (int)TBV);                             // 7
    }
}

// round 16
// speedup vs baseline: 1.0182x; 1.0182x over previous
#include <cuda_runtime.h>
#include <math.h>

#define HD 256
#define AD 64
#define VOCAB 32000
#define TS 64
#define BB 32
#define SQ 1024
#define H2 512
#define ROWS_TOT (TS*BB)
#define NB 64
#define NTILE 250

__device__ float g_embT[TS*HD*BB];             // [t][i][b]
__device__ float g_hT[2*HD*BB];                // ping-pong [p][k][b]
__device__ float g_ctxT[2*HD*BB];              // ping-pong [p][h][b]
__device__ float g_hid[HD*BB];                 // [j][b]
__device__ float g_c2[(size_t)BB*AD*SQ];       // [b][a][s]
__device__ float g_obuf[(size_t)ROWS_TOT*H2];
__device__ float g_qT[(size_t)HD*ROWS_TOT];    // fc1 out, k-major [k][r]
__device__ float g_f1w2T[HD*AD];
__device__ float g_f2w1T[HD*HD];
__device__ float g_f2w2T[HD*AD];
__device__ float g_fc1wT[H2*HD];
__device__ float g_fc2wT[(size_t)HD*VOCAB];
__device__ float g_pm[(size_t)ROWS_TOT*NTILE]; // per-(row,tile) max
__device__ float g_ps[(size_t)ROWS_TOT*NTILE]; // per-(row,tile) sumexp
__device__ float g_nll[ROWS_TOT];
__device__ float g_msk[ROWS_TOT];
__device__ unsigned g_bar;

__device__ __forceinline__ float2 ffma2(float2 a, float2 b, float2 c) {
    union U { float2 f; unsigned long long u; };
    U ua, ub, uc, ud; ua.f = a; ub.f = b; uc.f = c;
    asm("fma.rn.f32x2 %0, %1, %2, %3;" : "=l"(ud.u) : "l"(ua.u), "l"(ub.u), "l"(uc.u));
    return ud.f;
}
__device__ __forceinline__ float2 b2f(float w) { return make_float2(w, w); }
__device__ __forceinline__ float2 add2(float2 a, float2 b) { return make_float2(a.x+b.x, a.y+b.y); }

// ---- launch 1: fused prep: zero + small transposes + embT + fc2 transpose ----
__global__ void k_prep(const float* __restrict__ f2w1, const float* __restrict__ f2w2,
                       const float* __restrict__ f1w2, const float* __restrict__ fc1w,
                       const float* __restrict__ fc2w,
                       const int* __restrict__ yin, const float* __restrict__ emb) {
    __shared__ float tile[32][33];
    int bid = blockIdx.x, tid = threadIdx.x;
    if (bid == 0) {
        for (int i = tid; i < 2*HD*BB; i += 256) { g_hT[i] = 0.f; g_ctxT[i] = 0.f; }
        if (tid == 0) g_bar = 0u;
        return;
    }
    if (bid >= 289) {   // fc2 weight transpose: 8000 blocks
        int r2 = bid - 289;
        int bx = r2 & 7, by = r2 >> 3;
        int tx = tid & 31, ty = tid >> 5;
        int c0 = bx*32, r0 = by*32;
        for (int j = ty; j < 32; j += 8)
            tile[j][tx] = fc2w[(size_t)(r0 + j)*HD + c0 + tx];
        __syncthreads();
        for (int j = ty; j < 32; j += 8)
            g_fc2wT[(size_t)(c0 + j)*VOCAB + r0 + tx] = tile[tx][j];
        return;
    }
    if (bid >= 225) {   // embT: 64 blocks
        int t = bid - 225, i = tid;
        for (int b = 0; b < BB; b++)
            g_embT[((size_t)t*HD + i)*BB + b] = emb[(size_t)yin[t*BB + b]*HD + i];
        return;
    }
    const float* src; float* dst; int rows, cols, nbx;
    int r = bid - 1;
    if (r < 64)       { src = f2w1; dst = g_f2w1T; rows = HD; cols = HD; nbx = 8; }
    else if (r < 80)  { r -= 64; src = f2w2; dst = g_f2w2T; rows = AD; cols = HD; nbx = 8; }
    else if (r < 96)  { r -= 80; src = f1w2; dst = g_f1w2T; rows = AD; cols = HD; nbx = 8; }
    else              { r -= 96; src = fc1w; dst = g_fc1wT; rows = HD; cols = H2; nbx = 16; }
    int bx = r % nbx, by = r / nbx;
    int tx = tid & 31, ty = tid >> 5;
    int c0 = bx*32, r0 = by*32;
    for (int j = ty; j < 32; j += 8) {
        int rr = r0 + j, c = c0 + tx;
        if (rr < rows && c < cols) tile[j][tx] = src[(size_t)rr*cols + c];
    }
    __syncthreads();
    for (int j = ty; j < 32; j += 8) {
        int rr = r0 + tx, c = c0 + j;
        if (rr < rows && c < cols) dst[(size_t)c*rows + rr] = tile[tx][j];
    }
}

// ---- launch 2: c2, stored [b][a][s] ----
__global__ void k_c2(const float* __restrict__ yenc,
                     const float* __restrict__ b1, const float* __restrict__ b2) {
    __shared__ float2 ysp[HD][8];
    __shared__ float  hid[16][HD];
    int r0 = blockIdx.x*16, tid = threadIdx.x;
    float* ysf = (float*)ysp;
    for (int idx = tid; idx < 16*HD; idx += 256) {
        int r = idx >> 8, i = idx & 255;
        ysf[i*16 + r] = yenc[(size_t)(r0+r)*HD + i];
    }
    __syncthreads();
    {
        int j = tid; float bj = b1[j];
        float2 acc[8];
        #pragma unroll
        for (int p = 0; p < 8; p++) acc[p] = make_float2(bj, bj);
        for (int i = 0; i < HD; i++) {
            float2 wp = b2f(g_f2w1T[i*HD + j]);
            #pragma unroll
            for (int p = 0; p < 8; p++) acc[p] = ffma2(wp, ysp[i][p], acc[p]);
        }
        #pragma unroll
        for (int p = 0; p < 8; p++) {
            hid[2*p][j]   = fmaxf(acc[p].x, 0.f);
            hid[2*p+1][j] = fmaxf(acc[p].y, 0.f);
        }
    }
    __syncthreads();
    #pragma unroll
    for (int q = 0; q < 4; q++) {
        int o = tid + q*256, rr = o >> 6, a = o & 63;
        float acc = b2[a];
        for (int i = 0; i < HD; i++) acc = fmaf(hid[rr][i], g_f2w2T[i*AD + a], acc);
        int gr = r0 + rr, s = gr >> 5, b = gr & 31;
        g_c2[((size_t)b*AD + a)*SQ + s] = tanhf(acc);
    }
}

// ---- launch 3: persistent decode loop, 64 blocks x 256 threads (proven) ----
__global__ void __launch_bounds__(256, 1)
k_loop(const float* __restrict__ yenc,
       const float* __restrict__ wih, const float* __restrict__ bih,
       const float* __restrict__ whh, const float* __restrict__ bhh,
       const float* __restrict__ f1w1, const float* __restrict__ f1b1,
       const float* __restrict__ f1b2) {
    extern __shared__ float sdyn[];
    float2* sm2 = (float2*)sdyn;
    __shared__ float2 red[4][4][16][4];
    __shared__ float hred[256];
    __shared__ float s_hid[HD];
    __shared__ float c1s[AD];
    __shared__ float attw[SQ];
    __shared__ float2 cred[8][32][2];
    __shared__ float rsh[8];
    __shared__ float sh_mx, sh_sum;

    int g = blockIdx.x, tid = threadIdx.x;
    int kl = tid >> 6, ph = (tid >> 4) & 3, bp = tid & 15;
    int k = g*4 + kl;
    int ab = g >> 1, half = g & 1;
    unsigned bar = 0;
    const float* wihR = wih + (size_t)k*H2;
    const float* wihZ = wih + (size_t)(HD + k)*H2;
    const float* wihN = wih + (size_t)(2*HD + k)*H2;
    const float* whhR = whh + (size_t)k*HD;
    const float* whhZ = whh + (size_t)(HD + k)*HD;
    const float* whhN = whh + (size_t)(2*HD + k)*HD;
    const float2 z2 = make_float2(0.f, 0.f);

    for (int t = 0; t < TS; t++) {
        int cur = t & 1, nxt = cur ^ 1;
        {
            float4* d = (float4*)sdyn;
            const float4* se = (const float4*)(g_embT) + (size_t)t*2048;
            const float4* sc = (const float4*)(g_ctxT + (size_t)cur*HD*BB);
            const float4* sh = (const float4*)(g_hT   + (size_t)cur*HD*BB);
            for (int i = tid; i < 2048; i += 256) {
                d[i]        = se[i];
                d[2048 + i] = __ldcg(sc + i);
                d[4096 + i] = __ldcg(sh + i);
            }
        }
        __syncthreads();
        // ---- phase G: GRU ----
        {
            float2 ar = z2, az = z2, ani = z2, anh = z2;
            int pst = ph*192, pen = pst + 192;
            int mid = pen < 512 ? pen : (pst > 512 ? pst : 512);
            for (int p0 = pst; p0 < mid; p0 += 4) {
                float2 x0 = sm2[(p0+0)*16+bp], x1 = sm2[(p0+1)*16+bp];
                float2 x2 = sm2[(p0+2)*16+bp], x3 = sm2[(p0+3)*16+bp];
                float4 fr = *(const float4*)(wihR + p0);
                float4 fz = *(const float4*)(wihZ + p0);
                float4 fn = *(const float4*)(wihN + p0);
                ar = ffma2(b2f(fr.x),x0,ar); ar = ffma2(b2f(fr.y),x1,ar); ar = ffma2(b2f(fr.z),x2,ar); ar = ffma2(b2f(fr.w),x3,ar);
                az = ffma2(b2f(fz.x),x0,az); az = ffma2(b2f(fz.y),x1,az); az = ffma2(b2f(fz.z),x2,az); az = ffma2(b2f(fz.w),x3,az);
                ani= ffma2(b2f(fn.x),x0,ani);ani= ffma2(b2f(fn.y),x1,ani);ani= ffma2(b2f(fn.z),x2,ani);ani= ffma2(b2f(fn.w),x3,ani);
            }
            for (int p0 = mid; p0 < pen; p0 += 4) {
                float2 x0 = sm2[(p0+0)*16+bp], x1 = sm2[(p0+1)*16+bp];
                float2 x2 = sm2[(p0+2)*16+bp], x3 = sm2[(p0+3)*16+bp];
                int q = p0 - 512;
                float4 fr = *(const float4*)(whhR + q);
                float4 fz = *(const float4*)(whhZ + q);
                float4 fn = *(const float4*)(whhN + q);
                ar = ffma2(b2f(fr.x),x0,ar); ar = ffma2(b2f(fr.y),x1,ar); ar = ffma2(b2f(fr.z),x2,ar); ar = ffma2(b2f(fr.w),x3,ar);
                az = ffma2(b2f(fz.x),x0,az); az = ffma2(b2f(fz.y),x1,az); az = ffma2(b2f(fz.z),x2,az); az = ffma2(b2f(fz.w),x3,az);
                anh= ffma2(b2f(fn.x),x0,anh);anh= ffma2(b2f(fn.y),x1,anh);anh= ffma2(b2f(fn.z),x2,anh);anh= ffma2(b2f(fn.w),x3,anh);
            }
            red[ph][kl][bp][0] = ar; red[ph][kl][bp][1] = az;
            red[ph][kl][bp][2] = ani; red[ph][kl][bp][3] = anh;
        }
        __syncthreads();
        if (tid < 64) {
            int kk = tid >> 4, bq = tid & 15;
            int kg = g*4 + kk;
            float2 ar = z2, az = z2, ani = z2, anh = z2;
            #pragma unroll
            for (int q = 0; q < 4; q++) {
                ar  = add2(ar,  red[q][kk][bq][0]);
                az  = add2(az,  red[q][kk][bq][1]);
                ani = add2(ani, red[q][kk][bq][2]);
                anh = add2(anh, red[q][kk][bq][3]);
            }
            float br = bih[kg] + bhh[kg], bz = bih[HD+kg] + bhh[HD+kg];
            float bin = bih[2*HD+kg], bhn = bhh[2*HD+kg];
            float2 hprev = sm2[(512 + kg)*16 + bq];
            float rx = 1.f/(1.f + expf(-(ar.x + br)));
            float ry = 1.f/(1.f + expf(-(ar.y + br)));
            float zx = 1.f/(1.f + expf(-(az.x + bz)));
            float zy = 1.f/(1.f + expf(-(az.y + bz)));
            float nx = tanhf(ani.x + bin + rx*(anh.x + bhn));
            float ny = tanhf(ani.y + bin + ry*(anh.y + bhn));
            float2 hn = make_float2((1.f-zx)*nx + zx*hprev.x, (1.f-zy)*ny + zy*hprev.y);
            __stcg((float2*)(g_hT + (size_t)nxt*HD*BB) + (kg*16 + bq), hn);
            g_obuf[((size_t)t*BB + 2*bq)*H2 + kg]   = hn.x;
            g_obuf[((size_t)t*BB + 2*bq+1)*H2 + kg] = hn.y;
        }
        __syncthreads();
        if (tid == 0) { __threadfence(); atomicAdd(&g_bar, 1u);
            unsigned v; bar += NB;
            do { asm volatile("ld.acquire.gpu.b32 %0,[%1];":"=r"(v):"l"(&g_bar):"memory"); } while (v < bar);
        } else bar += NB;
        __syncthreads();

        // ---- phase H ----
        {
            float4* d = (float4*)sdyn;
            const float4* hn = (const float4*)(g_hT + (size_t)nxt*HD*BB);
            for (int i = tid; i < 2048; i += 256) d[i] = __ldcg(hn + i);
            __syncthreads();
            int hf = tid >> 7, jj = (tid >> 5) & 3, b = tid & 31;
            int j = g*4 + jj;
            const float* w = f1w1 + (size_t)j*HD + hf*128;
            float acc = 0.f;
            #pragma unroll 8
            for (int i4 = 0; i4 < 32; i4++) {
                float4 w4 = *(const float4*)(w + 4*i4);
                int ib = (hf*128 + 4*i4)*32 + b;
                acc = fmaf(w4.x, sdyn[ib],      acc);
                acc = fmaf(w4.y, sdyn[ib+32],   acc);
                acc = fmaf(w4.z, sdyn[ib+64],   acc);
                acc = fmaf(w4.w, sdyn[ib+96],   acc);
            }
            hred[tid] = acc;
        }
        __syncthreads();
        if (tid < 128) {
            int j = g*4 + (tid >> 5), b = tid & 31;
            float v = hred[tid] + hred[tid + 128] + f1b1[j];
            __stcg(&g_hid[j*32 + b], fmaxf(v, 0.f));
        }
        __syncthreads();
        if (tid == 0) { __threadfence(); atomicAdd(&g_bar, 1u);
            unsigned v; bar += NB;
            do { asm volatile("ld.acquire.gpu.b32 %0,[%1];":"=r"(v):"l"(&g_bar):"memory"); } while (v < bar);
        } else bar += NB;
        __syncthreads();

        // ---- phase A ----
        s_hid[tid] = __ldcg(&g_hid[tid*32 + ab]);
        __syncthreads();
        if (tid < AD) {
            float acc = 0.f;
            #pragma unroll 8
            for (int i = 0; i < HD; i++) acc = fmaf(g_f1w2T[i*AD + tid], s_hid[i], acc);
            c1s[tid] = tanhf(acc + f1b2[tid]);
        }
        __syncthreads();
        {
            int s0 = 4*tid;
            const float* c2b = g_c2 + (size_t)ab*AD*SQ;
            float4 sc = make_float4(0.f, 0.f, 0.f, 0.f);
            for (int a0 = 0; a0 < AD; a0 += 8) {
                float4 v[8];
                #pragma unroll
                for (int u = 0; u < 8; u++) v[u] = *(const float4*)(c2b + (size_t)(a0+u)*SQ + s0);
                #pragma unroll
                for (int u = 0; u < 8; u++) {
                    float ca = c1s[a0+u];
                    sc.x = fmaf(ca, v[u].x, sc.x); sc.y = fmaf(ca, v[u].y, sc.y);
                    sc.z = fmaf(ca, v[u].z, sc.z); sc.w = fmaf(ca, v[u].w, sc.w);
                }
            }
            float mloc = fmaxf(fmaxf(sc.x, sc.y), fmaxf(sc.z, sc.w));
            #pragma unroll
            for (int o = 16; o; o >>= 1) mloc = fmaxf(mloc, __shfl_xor_sync(~0u, mloc, o));
            if ((tid & 31) == 0) rsh[tid >> 5] = mloc;
            __syncthreads();
            if (tid == 0) { float v = rsh[0]; for (int w = 1; w < 8; w++) v = fmaxf(v, rsh[w]); sh_mx = v; }
            __syncthreads();
            float mx = sh_mx;
            sc.x = __expf(sc.x - mx); sc.y = __expf(sc.y - mx);
            sc.z = __expf(sc.z - mx); sc.w = __expf(sc.w - mx);
            float sl = sc.x + sc.y + sc.z + sc.w;
            #pragma unroll
            for (int o = 16; o; o >>= 1) sl += __shfl_xor_sync(~0u, sl, o);
            if ((tid & 31) == 0) rsh[tid >> 5] = sl;
            __syncthreads();
            if (tid == 0) { float v = 0.f; for (int w = 0; w < 8; w++) v += rsh[w]; sh_sum = v; }
            __syncthreads();
            float inv = 1.f / sh_sum;
            *(float4*)&attw[s0] = make_float4(sc.x*inv, sc.y*inv, sc.z*inv, sc.w*inv);
        }
        __syncthreads();
        {
            int v = tid & 31, strip = tid >> 5;
            int h0 = half*128;
            float2 a0 = z2, a1 = z2;
            for (int o8 = 0; o8 < 128; o8 += 8) {
                float4 y[8]; float aw[8];
                #pragma unroll
                for (int u = 0; u < 8; u++) {
                    int s = strip*128 + o8 + u;
                    y[u] = *(const float4*)(yenc + ((size_t)s*BB + ab)*HD + h0 + 4*v);
                    aw[u] = attw[s];
                }
                #pragma unroll
                for (int u = 0; u < 8; u++) {
                    a0 = ffma2(b2f(aw[u]), make_float2(y[u].x, y[u].y), a0);
                    a1 = ffma2(b2f(aw[u]), make_float2(y[u].z, y[u].w), a1);
                }
            }
            cred[strip][v][0] = a0; cred[strip][v][1] = a1;
            __syncthreads();
            if (tid < 32) {
                float2 s0 = z2, s1 = z2;
                #pragma unroll
                for (int w = 0; w < 8; w++) { s0 = add2(s0, cred[w][tid][0]); s1 = add2(s1, cred[w][tid][1]); }
                int hh = h0 + 4*tid;
                float* cb = g_ctxT + (size_t)nxt*HD*BB;
                __stcg(&cb[(hh+0)*32 + ab], s0.x);
                __stcg(&cb[(hh+1)*32 + ab], s0.y);
                __stcg(&cb[(hh+2)*32 + ab], s1.x);
                __stcg(&cb[(hh+3)*32 + ab], s1.y);
                *(float4*)&g_obuf[((size_t)t*BB + ab)*H2 + HD + hh] = make_float4(s0.x, s0.y, s1.x, s1.y);
            }
        }
        __syncthreads();
        if (tid == 0) { __threadfence(); atomicAdd(&g_bar, 1u);
            unsigned v; bar += NB;
            do { asm volatile("ld.acquire.gpu.b32 %0,[%1];":"=r"(v):"l"(&g_bar):"memory"); } while (v < bar);
        } else bar += NB;
        __syncthreads();
    }
}

// ---- launch 4 (PROFILED): fc1 -> g_qT (k-major), MLP-8 weight loads ----
__global__ void k_fc1(const float* __restrict__ fc1b) {
    __shared__ float2 xsp[H2][8];
    int r0 = blockIdx.x*16, tid = threadIdx.x;
    float* xsf = (float*)xsp;
    for (int idx = tid; idx < 16*H2; idx += 256) {
        int r = idx >> 9, i = idx & 511;
        xsf[i*16 + r] = g_obuf[(size_t)(r0+r)*H2 + i];
    }
    __syncthreads();
    int j = tid; float bj = fc1b[j];
    float2 acc[8];
    #pragma unroll
    for (int p = 0; p < 8; p++) acc[p] = make_float2(bj, bj);
    #pragma unroll 8
    for (int i = 0; i < H2; i++) {
        float2 wp = b2f(g_fc1wT[i*HD + j]);
        #pragma unroll
        for (int p = 0; p < 8; p++) acc[p] = ffma2(wp, xsp[i][p], acc[p]);
    }
    #pragma unroll
    for (int p = 0; p < 8; p++) {
        g_qT[(size_t)j*ROWS_TOT + r0 + 2*p]   = fmaxf(acc[p].x, 0.f);
        g_qT[(size_t)j*ROWS_TOT + r0 + 2*p+1] = fmaxf(acc[p].y, 0.f);
    }
}

// ---- launch 5: tiled fc2 (R13 proven) + fused per-(row,tile) softmax partials ----
#define FBM 64
#define FBN 128
#define FKC 64
__global__ void __launch_bounds__(256) k_fc2(const float* __restrict__ fc2b, float* __restrict__ preds) {
    __shared__ float qs[FKC][FBM];
    __shared__ float ws[FKC][FBN];
    int tid = threadIdx.x;
    int tile = blockIdx.x;
    int nb = tile * FBN, rb = blockIdx.y * FBM;
    int tm = tid >> 5, tn = tid & 31;
    float2 acc[8][2];
    #pragma unroll
    for (int i = 0; i < 8; i++) { acc[i][0] = make_float2(0.f,0.f); acc[i][1] = make_float2(0.f,0.f); }
    for (int kc = 0; kc < HD; kc += FKC) {
        __syncthreads();
        #pragma unroll
        for (int u = 0; u < 4; u++) {
            int idx = tid + u*256;
            int kk = idx >> 4, rf = idx & 15;
            *(float4*)&qs[kk][rf*4] = *(const float4*)&g_qT[(size_t)(kc+kk)*ROWS_TOT + rb + rf*4];
        }
        #pragma unroll
        for (int u = 0; u < 8; u++) {
            int idx = tid + u*256;
            int kk = idx >> 5, nf = idx & 31;
            *(float4*)&ws[kk][nf*4] = *(const float4*)&g_fc2wT[(size_t)(kc+kk)*VOCAB + nb + nf*4];
        }
        __syncthreads();
        #pragma unroll 2
        for (int kk = 0; kk < FKC; kk++) {
            float4 bfr = *(const float4*)&ws[kk][tn*4];
            float4 a0  = *(const float4*)&qs[kk][tm*8];
            float4 a1  = *(const float4*)&qs[kk][tm*8 + 4];
            float2 b01 = make_float2(bfr.x, bfr.y), b23 = make_float2(bfr.z, bfr.w);
            acc[0][0] = ffma2(b2f(a0.x), b01, acc[0][0]); acc[0][1] = ffma2(b2f(a0.x), b23, acc[0][1]);
            acc[1][0] = ffma2(b2f(a0.y), b01, acc[1][0]); acc[1][1] = ffma2(b2f(a0.y), b23, acc[1][1]);
            acc[2][0] = ffma2(b2f(a0.z), b01, acc[2][0]); acc[2][1] = ffma2(b2f(a0.z), b23, acc[2][1]);
            acc[3][0] = ffma2(b2f(a0.w), b01, acc[3][0]); acc[3][1] = ffma2(b2f(a0.w), b23, acc[3][1]);
            acc[4][0] = ffma2(b2f(a1.x), b01, acc[4][0]); acc[4][1] = ffma2(b2f(a1.x), b23, acc[4][1]);
            acc[5][0] = ffma2(b2f(a1.y), b01, acc[5][0]); acc[5][1] = ffma2(b2f(a1.y), b23, acc[5][1]);
            acc[6][0] = ffma2(b2f(a1.z), b01, acc[6][0]); acc[6][1] = ffma2(b2f(a1.z), b23, acc[6][1]);
            acc[7][0] = ffma2(b2f(a1.w), b01, acc[7][0]); acc[7][1] = ffma2(b2f(a1.w), b23, acc[7][1]);
        }
    }
    int n0 = nb + tn*4;
    float4 bv = *(const float4*)&fc2b[n0];
    #pragma unroll
    for (int i = 0; i < 8; i++) {
        float4 o = make_float4(acc[i][0].x + bv.x, acc[i][0].y + bv.y,
                               acc[i][1].x + bv.z, acc[i][1].y + bv.w);
        int row = rb + tm*8 + i;
        *(float4*)&preds[(size_t)row*VOCAB + n0] = o;
        float lm = fmaxf(fmaxf(o.x, o.y), fmaxf(o.z, o.w));
        #pragma unroll
        for (int of = 16; of; of >>= 1) lm = fmaxf(lm, __shfl_xor_sync(~0u, lm, of));
        float se = __expf(o.x - lm) + __expf(o.y - lm) + __expf(o.z - lm) + __expf(o.w - lm);
        #pragma unroll
        for (int of = 16; of; of >>= 1) se += __shfl_xor_sync(~0u, se, of);
        if (tn == 0) {
            g_pm[(size_t)row*NTILE + tile] = lm;
            g_ps[(size_t)row*NTILE + tile] = se;
        }
    }
}

// ---- launch 6: combine per-tile partials -> nll ----
__global__ void k_loss_combine(const float* __restrict__ preds, const int* __restrict__ yout) {
    __shared__ float rm[8], rs[8];
    int row = blockIdx.x, tid = threadIdx.x;
    float m = -1e30f, s = 0.f;
    if (tid < NTILE) {
        m = g_pm[(size_t)row*NTILE + tid];
        s = g_ps[(size_t)row*NTILE + tid];
    }
    #pragma unroll
    for (int o = 16; o; o >>= 1) {
        float mo = __shfl_xor_sync(~0u, m, o);
        float so = __shfl_xor_sync(~0u, s, o);
        float nm = fmaxf(m, mo);
        s = s*__expf(m - nm) + so*__expf(mo - nm);
        m = nm;
    }
    if ((tid & 31) == 0) { rm[tid >> 5] = m; rs[tid >> 5] = s; }
    __syncthreads();
    if (tid == 0) {
        float M = rm[0], S = rs[0];
        for (int w = 1; w < 8; w++) {
            float nm = fmaxf(M, rm[w]);
            S = S*__expf(M - nm) + rs[w]*__expf(rm[w] - nm);
            M = nm;
        }
        int tgt = yout[row];
        float msk = (tgt != 0) ? 1.f : 0.f;
        g_nll[row] = (M + logf(S) - preds[(size_t)row*VOCAB + tgt]) * msk;
        g_msk[row] = msk;
    }
}

// ---- launch 7: final loss reduce ----
__global__ void k_loss_final(float* __restrict__ out, int oi) {
    __shared__ float ra[8], rb[8];
    int tid = threadIdx.x;
    float a = 0.f, b = 0.f;
    for (int r = tid; r < ROWS_TOT; r += 256) { a += g_nll[r]; b += g_msk[r]; }
    #pragma unroll
    for (int o = 16; o; o >>= 1) { a += __shfl_xor_sync(~0u, a, o); b += __shfl_xor_sync(~0u, b, o); }
    if ((tid & 31) == 0) { ra[tid >> 5] = a; rb[tid >> 5] = b; }
    __syncthreads();
    if (tid == 0) {
        float sa = 0.f, sb = 0.f;
        for (int w = 0; w < 8; w++) { sa += ra[w]; sb += rb[w]; }
        out[oi] = sa / fmaxf(sb, 1.f);
    }
}

extern "C" void kernel_launch(void* const* d_in, const int* in_sizes, int n_in,
                              void* d_out, int out_size) {
    const int*   y_in  = (const int*)  d_in[0];
    const int*   y_out = (const int*)  d_in[1];
    const float* y_enc = (const float*)d_in[2];
    const float* emb   = (const float*)d_in[4];
    const float* f1_w1 = (const float*)d_in[5];
    const float* f1_b1 = (const float*)d_in[6];
    const float* f1_w2 = (const float*)d_in[7];
    const float* f1_b2 = (const float*)d_in[8];
    const float* f2_w1 = (const float*)d_in[9];
    const float* f2_b1 = (const float*)d_in[10];
    const float* f2_w2 = (const float*)d_in[11];
    const float* f2_b2 = (const float*)d_in[12];
    const float* g_wih = (const float*)d_in[13];
    const float* g_bih = (const float*)d_in[14];
    const float* g_whh = (const float*)d_in[15];
    const float* g_bhh = (const float*)d_in[16];
    const float* fc1_w = (const float*)d_in[17];
    const float* fc1_b = (const float*)d_in[18];
    const float* fc2_w = (const float*)d_in[19];
    const float* fc2_b = (const float*)d_in[20];

    float* preds = (float*)d_out;
    const long long TBV = (long long)TS*BB*VOCAB;

    cudaFuncSetAttribute(k_loop, cudaFuncAttributeMaxDynamicSharedMemorySize, 98304);

    k_prep<<<289 + 8000, 256>>>(f2_w1, f2_w2, f1_w2, fc1_w, fc2_w, y_in, emb); // 1
    k_c2<<<(SQ*BB)/16, 256>>>(y_enc, f2_b1, f2_b2);                            // 2
    k_loop<<<NB, 256, 98304>>>(y_enc, g_wih, g_bih, g_whh, g_bhh,
                               f1_w1, f1_b1, f1_b2);                           // 3
    k_fc1<<<ROWS_TOT/16, 256>>>(fc1_b);                                        // 4 <- profiled
    k_fc2<<<dim3(NTILE, ROWS_TOT/FBM), 256>>>(fc2_b, preds);                   // 5
    if ((long long)out_size >= TBV + 1) {
        k_loss_combine<<<ROWS_TOT, 256>>>(preds, y_out);                       // 6
        k_loss_final<<<1, 256>>>(preds, (int)TBV);                             // 7
    }
}